// round 1
// baseline (speedup 1.0000x reference)
#include <cuda_runtime.h>
#include <cstdint>

#define BATCH  4
#define DMODEL 1024
#define NSTATE 64
#define LSEQ   2048
#define MROWS  1152   // 1024 (Delta) + 64 (Bm) + 64 (Cm)

// ---------------- device scratch (allocation-free) ----------------
__device__ float g_W[MROWS * DMODEL];                     // [Delta; Bm; Cm]  ~4.7 MB
__device__ float g_S[(size_t)BATCH * MROWS * LSEQ];       // [delta; Bu; Cu] per batch ~37.7 MB

// ---------------- f32x2 packed helpers ----------------
__device__ __forceinline__ uint64_t dup2(float x) {
    uint64_t r; asm("mov.b64 %0, {%1, %1};" : "=l"(r) : "f"(x)); return r;
}
__device__ __forceinline__ uint64_t mul2(uint64_t a, uint64_t b) {
    uint64_t r; asm("mul.rn.f32x2 %0, %1, %2;" : "=l"(r) : "l"(a), "l"(b)); return r;
}
__device__ __forceinline__ uint64_t fma2(uint64_t a, uint64_t b, uint64_t c) {
    uint64_t r; asm("fma.rn.f32x2 %0, %1, %2, %3;" : "=l"(r) : "l"(a), "l"(b), "l"(c)); return r;
}
__device__ __forceinline__ float2 u64_f2(uint64_t v) {
    float2 f; asm("mov.b64 {%0, %1}, %2;" : "=f"(f.x), "=f"(f.y) : "l"(v)); return f;
}

// ---------------- kernel 0: pack W = [Delta; Bm; Cm] ----------------
__global__ __launch_bounds__(256) void pack_w_kernel(
    const float* __restrict__ Delta,
    const float* __restrict__ Bm,
    const float* __restrict__ Cm)
{
    int i = blockIdx.x * 256 + threadIdx.x;
    const int total = MROWS * DMODEL;
    if (i >= total) return;
    int r = i >> 10;          // / DMODEL
    int c = i & 1023;         // % DMODEL
    float v;
    if (r < 1024)      v = Delta[r * DMODEL + c];
    else if (r < 1088) v = Bm[(r - 1024) * DMODEL + c];
    else               v = Cm[(r - 1088) * DMODEL + c];
    g_W[i] = v;
}

// ---------------- kernel 1: SGEMM  g_S[b] = g_W @ u[b] ----------------
// C[MROWS, LSEQ] = W[MROWS, DMODEL] x U[DMODEL, LSEQ], per batch.
// 128x128x16 tiles, 256 threads, 8x8 per thread, packed f32x2 FMA.
#define GBM 128
#define GBN 128
#define GBK 16

__global__ __launch_bounds__(256) void gemm_kernel(const float* __restrict__ u)
{
    const int b  = blockIdx.z;
    const float* __restrict__ Bmat = u + (size_t)b * DMODEL * LSEQ;
    float* __restrict__ Cmat = g_S + (size_t)b * MROWS * LSEQ;
    const int m0 = blockIdx.y * GBM;
    const int n0 = blockIdx.x * GBN;

    __shared__ __align__(16) float As[GBK][GBM + 4];
    __shared__ __align__(16) float Bs[GBK][GBN + 4];

    const int tid = threadIdx.x;
    const int tx  = tid & 15;   // 0..15 -> n direction
    const int ty  = tid >> 4;   // 0..15 -> m direction

    uint64_t acc[8][4];
#pragma unroll
    for (int i = 0; i < 8; i++)
#pragma unroll
        for (int j = 0; j < 4; j++) acc[i][j] = 0ull;

    for (int k0 = 0; k0 < DMODEL; k0 += GBK) {
        // A tile: 128 rows x 16 k, transposed into As[k][m]
#pragma unroll
        for (int t = 0; t < 2; t++) {
            int f4 = tid + 256 * t;         // 0..511
            int ar = f4 >> 2;               // 0..127
            int ac = (f4 & 3) * 4;          // 0,4,8,12
            float4 av = *(const float4*)(g_W + (size_t)(m0 + ar) * DMODEL + k0 + ac);
            As[ac + 0][ar] = av.x;
            As[ac + 1][ar] = av.y;
            As[ac + 2][ar] = av.z;
            As[ac + 3][ar] = av.w;
        }
        // B tile: 16 k x 128 n, direct copy
#pragma unroll
        for (int t = 0; t < 2; t++) {
            int f4 = tid + 256 * t;         // 0..511
            int br = f4 >> 5;               // 0..15
            int bc = (f4 & 31) * 4;         // 0..124
            *(float4*)&Bs[br][bc] =
                *(const float4*)(Bmat + (size_t)(k0 + br) * LSEQ + n0 + bc);
        }
        __syncthreads();

#pragma unroll
        for (int kk = 0; kk < GBK; kk++) {
            float4 a0 = *(const float4*)&As[kk][ty * 8];
            float4 a1 = *(const float4*)&As[kk][ty * 8 + 4];
            float a[8] = {a0.x, a0.y, a0.z, a0.w, a1.x, a1.y, a1.z, a1.w};
            const uint64_t* bp = (const uint64_t*)&Bs[kk][tx * 8];
            uint64_t bb[4] = {bp[0], bp[1], bp[2], bp[3]};
#pragma unroll
            for (int i = 0; i < 8; i++) {
                uint64_t ad = dup2(a[i]);
#pragma unroll
                for (int j = 0; j < 4; j++)
                    acc[i][j] = fma2(ad, bb[j], acc[i][j]);
            }
        }
        __syncthreads();
    }

#pragma unroll
    for (int i = 0; i < 8; i++) {
        float* crow = Cmat + (size_t)(m0 + ty * 8 + i) * LSEQ + n0 + tx * 8;
        float2 v0 = u64_f2(acc[i][0]);
        float2 v1 = u64_f2(acc[i][1]);
        float2 v2 = u64_f2(acc[i][2]);
        float2 v3 = u64_f2(acc[i][3]);
        float4 w0 = {v0.x, v0.y, v1.x, v1.y};
        float4 w1 = {v2.x, v2.y, v3.x, v3.y};
        *(float4*)crow       = w0;
        *(float4*)(crow + 4) = w1;
    }
}

// ---------------- kernel 2: sequential scan over L ----------------
// Block: one batch b, 32 d-values. 8 threads per d, each owns 8 n-states
// (4 f32x2 pairs) in registers for the whole sequence.
#define DT  32     // d per block
#define TL  32     // l per shared tile
#define SBS 66     // sBu/sCu row stride (floats): [l][n], 8B-aligned, conflict-light
#define SDS 36     // sDe/sU/sY row stride (floats): [d][l], 16B-aligned rows

__global__ __launch_bounds__(256) void scan_kernel(
    const float* __restrict__ u,
    const float* __restrict__ A,
    const float* __restrict__ Dv,
    float* __restrict__ y)
{
    const int b  = blockIdx.y;
    const int d0 = blockIdx.x * DT;

    const float* __restrict__ de = g_S + (size_t)b * MROWS * LSEQ;          // delta rows 0..1023
    const float* __restrict__ Bu = de + (size_t)1024 * LSEQ;                // rows 1024..1087
    const float* __restrict__ Cu = de + (size_t)1088 * LSEQ;                // rows 1088..1151
    const float* __restrict__ ub = u + (size_t)b * DMODEL * LSEQ;

    __shared__ __align__(16) float sBu[TL][SBS];
    __shared__ __align__(16) float sCu[TL][SBS];
    __shared__ __align__(16) float sDe[DT][SDS];
    __shared__ __align__(16) float sU [DT][SDS];
    __shared__ __align__(16) float sY [DT][SDS];

    const int tid = threadIdx.x;
    const int dl  = tid >> 3;   // 0..31 local d
    const int c   = tid & 7;    // 0..7  n-chunk
    const int n0  = c * 8;

    uint64_t A2[4];
#pragma unroll
    for (int p = 0; p < 4; p++)
        A2[p] = *(const uint64_t*)&A[n0 + 2 * p];   // pairs of A, 8B aligned

    const float Dd = Dv[d0 + dl];

    uint64_t h2[4] = {0ull, 0ull, 0ull, 0ull};

    for (int l0 = 0; l0 < LSEQ; l0 += TL) {
        __syncthreads();   // previous tile fully consumed

        // Bu/Cu tile: 64 n x 32 l, transposed to [l][n]
#pragma unroll
        for (int t = 0; t < 2; t++) {
            int f4 = tid + 256 * t;    // 0..511
            int n  = f4 >> 3;          // 0..63
            int q  = f4 & 7;           // 0..7 -> l quad
            float4 v = *(const float4*)(Bu + (size_t)n * LSEQ + l0 + q * 4);
            sBu[q * 4 + 0][n] = v.x;
            sBu[q * 4 + 1][n] = v.y;
            sBu[q * 4 + 2][n] = v.z;
            sBu[q * 4 + 3][n] = v.w;
            float4 w = *(const float4*)(Cu + (size_t)n * LSEQ + l0 + q * 4);
            sCu[q * 4 + 0][n] = w.x;
            sCu[q * 4 + 1][n] = w.y;
            sCu[q * 4 + 2][n] = w.z;
            sCu[q * 4 + 3][n] = w.w;
        }
        // delta / u tiles: 32 d x 32 l, direct [d][l]
        {
            int dd = tid >> 3;
            int q  = tid & 7;
            *(float4*)&sDe[dd][q * 4] =
                *(const float4*)(de + (size_t)(d0 + dd) * LSEQ + l0 + q * 4);
            *(float4*)&sU[dd][q * 4] =
                *(const float4*)(ub + (size_t)(d0 + dd) * LSEQ + l0 + q * 4);
        }
        __syncthreads();

#pragma unroll 8
        for (int l = 0; l < TL; l++) {
            float ds = sDe[dl][l];
            float us = sU[dl][l];
            float du = ds * us;
            uint64_t d2  = dup2(ds);
            uint64_t du2 = dup2(du);
            uint64_t y2  = 0ull;
            const uint64_t* bup = (const uint64_t*)&sBu[l][n0];
            const uint64_t* cup = (const uint64_t*)&sCu[l][n0];
#pragma unroll
            for (int p = 0; p < 4; p++) {
                uint64_t dA = mul2(d2, A2[p]);           // delta*A_n
                uint64_t pb = mul2(du2, bup[p]);         // delta*u*Bu_n
                h2[p] = fma2(dA, h2[p], pb);             // h = dA*h + pb
                y2    = fma2(cup[p], h2[p], y2);         // y += Cu_n*h
            }
            float2 yf = u64_f2(y2);
            float yv = yf.x + yf.y;
#pragma unroll
            for (int m = 1; m < 8; m <<= 1)
                yv += __shfl_xor_sync(0xffffffffu, yv, m);
            if (c == 0) sY[dl][l] = yv;
        }
        __syncthreads();

        // writeback: y + u*D, vectorized
        {
            int dd = tid >> 3;
            int q  = tid & 7;
            float4 yv = *(const float4*)&sY[dd][q * 4];
            float4 uv = *(const float4*)&sU[dd][q * 4];
            float4 o;
            o.x = yv.x + uv.x * Dd;
            o.y = yv.y + uv.y * Dd;
            o.z = yv.z + uv.z * Dd;
            o.w = yv.w + uv.w * Dd;
            *(float4*)(y + ((size_t)b * DMODEL + d0 + dd) * LSEQ + l0 + q * 4) = o;
        }
    }
}

// ---------------- host launcher ----------------
extern "C" void kernel_launch(void* const* d_in, const int* in_sizes, int n_in,
                              void* d_out, int out_size)
{
    // Resolve inputs by element count (robust to whether scalar L is passed):
    // u: 4*1024*2048=8388608, A: 64, Bm/Cm: 65536 each (Bm first), D: 1024, Delta: 1048576
    const float* u  = nullptr;
    const float* A  = nullptr;
    const float* Bm = nullptr;
    const float* Cm = nullptr;
    const float* D  = nullptr;
    const float* De = nullptr;
    for (int i = 0; i < n_in; i++) {
        int s = in_sizes[i];
        const float* p = (const float*)d_in[i];
        if      (s == 8388608 && !u)  u  = p;
        else if (s == 64      && !A)  A  = p;
        else if (s == 65536) { if (!Bm) Bm = p; else if (!Cm) Cm = p; }
        else if (s == 1024    && !D)  D  = p;
        else if (s == 1048576 && !De) De = p;
    }
    float* y = (float*)d_out;
    (void)out_size;

    // 1) pack W = [Delta; Bm; Cm]
    {
        int total = MROWS * DMODEL;
        pack_w_kernel<<<(total + 255) / 256, 256>>>(De, Bm, Cm);
    }
    // 2) fused projection GEMM: g_S[b] = W @ u[b]
    {
        dim3 grid(LSEQ / GBN, MROWS / GBM, BATCH);   // 16 x 9 x 4
        gemm_kernel<<<grid, 256>>>(u);
    }
    // 3) sequential scan + output
    {
        dim3 grid(DMODEL / DT, BATCH);               // 32 x 4
        scan_kernel<<<grid, 256>>>(u, A, D, y);
    }
}

// round 9
// speedup vs baseline: 1.4649x; 1.4649x over previous
#include <cuda_runtime.h>
#include <cstdint>

#define BATCH  4
#define DMODEL 1024
#define NSTATE 64
#define LSEQ   2048
#define MROWS  1152   // 1024 (Delta) + 64 (Bm) + 64 (Cm)

// ---------------- device scratch (allocation-free) ----------------
__device__ __align__(256) float g_W[MROWS * DMODEL];                 // packed [Delta; Bm; Cm]
__device__ __align__(256) float g_S[(size_t)BATCH * MROWS * LSEQ];   // [delta; Bu; Cu] per batch

// ---------------- f32x2 packed helpers (scan) ----------------
__device__ __forceinline__ uint64_t dup2(float x) {
    uint64_t r; asm("mov.b64 %0, {%1, %1};" : "=l"(r) : "f"(x)); return r;
}
__device__ __forceinline__ uint64_t mul2(uint64_t a, uint64_t b) {
    uint64_t r; asm("mul.rn.f32x2 %0, %1, %2;" : "=l"(r) : "l"(a), "l"(b)); return r;
}
__device__ __forceinline__ uint64_t fma2(uint64_t a, uint64_t b, uint64_t c) {
    uint64_t r; asm("fma.rn.f32x2 %0, %1, %2, %3;" : "=l"(r) : "l"(a), "l"(b), "l"(c)); return r;
}
__device__ __forceinline__ float2 u64_f2(uint64_t v) {
    float2 f; asm("mov.b64 {%0, %1}, %2;" : "=f"(f.x), "=f"(f.y) : "l"(v)); return f;
}

// ---------------- tf32 helpers ----------------
__device__ __forceinline__ uint32_t tf32b(float x) {
    uint32_t r; asm("cvt.rna.tf32.f32 %0, %1;" : "=r"(r) : "f"(x));
    return r;
}

// mma.sync m16n8k8 tf32 (base ISA, sm_80+, compiles for plain sm_103)
__device__ __forceinline__ void mma_tf32(float* c, const uint32_t* a, const uint32_t* b) {
    asm volatile("mma.sync.aligned.m16n8k8.row.col.f32.tf32.tf32.f32 "
        "{%0,%1,%2,%3}, {%4,%5,%6,%7}, {%8,%9}, {%0,%1,%2,%3};"
        : "+f"(c[0]), "+f"(c[1]), "+f"(c[2]), "+f"(c[3])
        : "r"(a[0]), "r"(a[1]), "r"(a[2]), "r"(a[3]), "r"(b[0]), "r"(b[1]));
}

__device__ __forceinline__ void cpasync16(uint32_t dst, const void* src) {
    asm volatile("cp.async.cg.shared.global [%0], [%1], 16;" :: "r"(dst), "l"(src) : "memory");
}
__device__ __forceinline__ uint32_t smem_u32(const void* p) {
    uint32_t a;
    asm("{ .reg .u64 t; cvta.to.shared.u64 t, %1; cvt.u32.u64 %0, t; }" : "=r"(a) : "l"(p));
    return a;
}
#define CP_COMMIT() asm volatile("cp.async.commit_group;" ::: "memory")

// ---------------- kernel 0: pack W = [Delta; Bm; Cm] ----------------
__global__ __launch_bounds__(256) void pack_w_kernel(
    const float* __restrict__ Delta, const float* __restrict__ Bm, const float* __restrict__ Cm)
{
    int i = blockIdx.x * 256 + threadIdx.x;
    if (i >= MROWS * DMODEL) return;
    int r = i >> 10, c = i & 1023;
    float v;
    if (r < 1024)      v = Delta[r * DMODEL + c];
    else if (r < 1088) v = Bm[(r - 1024) * DMODEL + c];
    else               v = Cm[(r - 1088) * DMODEL + c];
    g_W[i] = v;
}

// ---------------- kernel 1: tf32 mma.sync GEMM  g_S[b] = g_W @ u[b] ----------------
#define BM 128
#define BN 128
#define BK 32
#define ASTR 36                  // A smem row stride (floats): (4g+tg) conflict-free
#define BSTR 136                 // B smem row stride (floats): (8tg+g) conflict-free
#define AF (BM * ASTR)           // 4608 floats
#define BF (BK * BSTR)           // 4352 floats
#define STF (AF + BF)            // 8960 floats per stage
#define SMEM_G (2 * STF * 4)     // 71680 bytes
#define NCHUNK (DMODEL / BK)     // 32

__device__ __forceinline__ void load_chunk_g(int tid, int c, int m0, int n0,
                                             const float* __restrict__ Ub,
                                             uint32_t aSm, uint32_t bSm)
{
    const float* Wt = g_W + (size_t)m0 * DMODEL + c * BK;
#pragma unroll
    for (int i = 0; i < 4; i++) {                 // A: 128 rows x 32 floats = 1024 granules
        int t = tid + 256 * i;
        int r = t >> 3, j = t & 7;
        cpasync16(aSm + r * (ASTR * 4) + j * 16, Wt + (size_t)r * DMODEL + j * 4);
    }
    const float* Ut = Ub + (size_t)(c * BK) * LSEQ + n0;
#pragma unroll
    for (int i = 0; i < 4; i++) {                 // B: 32 rows x 128 floats = 1024 granules
        int t = tid + 256 * i;
        int k = t >> 5, j = t & 31;
        cpasync16(bSm + k * (BSTR * 4) + j * 16, Ut + (size_t)k * LSEQ + j * 4);
    }
}

__global__ __launch_bounds__(256, 2) void gemm_mma_kernel(const float* __restrict__ u)
{
    extern __shared__ __align__(16) float sm[];
    const int tid  = threadIdx.x;
    const int wid  = tid >> 5, lane = tid & 31;
    const int wm   = wid & 3, wn = wid >> 2;      // 4 m-warps x 2 n-warps
    const int g    = lane >> 2, tg = lane & 3;

    const int b  = blockIdx.z;
    const int m0 = blockIdx.y * BM;
    const int n0 = blockIdx.x * BN;
    const float* __restrict__ Ub = u + (size_t)b * DMODEL * LSEQ;
    float* __restrict__ Cb = g_S + (size_t)b * MROWS * LSEQ;

    const uint32_t sb = smem_u32(sm);
    const uint32_t aSm[2] = {sb, sb + STF * 4};
    const uint32_t bSm[2] = {sb + AF * 4, sb + STF * 4 + AF * 4};
    const float* aP[2] = {sm, sm + STF};
    const float* bP[2] = {sm + AF, sm + STF + AF};

    float acc[2][8][4];
#pragma unroll
    for (int mt = 0; mt < 2; mt++)
#pragma unroll
        for (int nt = 0; nt < 8; nt++)
#pragma unroll
            for (int q = 0; q < 4; q++) acc[mt][nt][q] = 0.f;

    load_chunk_g(tid, 0, m0, n0, Ub, aSm[0], bSm[0]);
    CP_COMMIT();

    for (int c = 0; c < NCHUNK; c++) {
        const int s = c & 1;
        if (c + 1 < NCHUNK) {
            load_chunk_g(tid, c + 1, m0, n0, Ub, aSm[1 - s], bSm[1 - s]);
            CP_COMMIT();
            asm volatile("cp.async.wait_group 1;" ::: "memory");
        } else {
            asm volatile("cp.async.wait_group 0;" ::: "memory");
        }
        __syncthreads();

        const float* As = aP[s];
        const float* Bs = bP[s];
#pragma unroll
        for (int ks = 0; ks < 4; ks++) {
            const int k0 = ks * 8;
            uint32_t af[2][4];
#pragma unroll
            for (int mt = 0; mt < 2; mt++) {
                int row = wm * 32 + mt * 16;
                af[mt][0] = tf32b(As[(row + g)     * ASTR + k0 + tg]);
                af[mt][1] = tf32b(As[(row + g + 8) * ASTR + k0 + tg]);
                af[mt][2] = tf32b(As[(row + g)     * ASTR + k0 + tg + 4]);
                af[mt][3] = tf32b(As[(row + g + 8) * ASTR + k0 + tg + 4]);
            }
            uint32_t bf[8][2];
#pragma unroll
            for (int nt = 0; nt < 8; nt++) {
                int col = wn * 64 + nt * 8 + g;
                bf[nt][0] = tf32b(Bs[(k0 + tg)     * BSTR + col]);
                bf[nt][1] = tf32b(Bs[(k0 + tg + 4) * BSTR + col]);
            }
#pragma unroll
            for (int mt = 0; mt < 2; mt++)
#pragma unroll
                for (int nt = 0; nt < 8; nt++)
                    mma_tf32(acc[mt][nt], af[mt], bf[nt]);
        }
        __syncthreads();
    }

    // epilogue: direct STG, 32B-contiguous per 4-lane group
#pragma unroll
    for (int mt = 0; mt < 2; mt++) {
        int row0 = m0 + wm * 32 + mt * 16 + g;
#pragma unroll
        for (int nt = 0; nt < 8; nt++) {
            int col = n0 + wn * 64 + nt * 8 + 2 * tg;
            float2 v0 = {acc[mt][nt][0], acc[mt][nt][1]};
            float2 v1 = {acc[mt][nt][2], acc[mt][nt][3]};
            *(float2*)(Cb + (size_t)row0 * LSEQ + col)       = v0;
            *(float2*)(Cb + (size_t)(row0 + 8) * LSEQ + col) = v1;
        }
    }
}

// ---------------- kernel 2: sequential scan over L (round-1 known-good) ----------------
#define DT  32
#define TL  32
#define SBS 66
#define SDS 36

__global__ __launch_bounds__(256) void scan_kernel(
    const float* __restrict__ u, const float* __restrict__ A,
    const float* __restrict__ Dv, float* __restrict__ y)
{
    const int b  = blockIdx.y;
    const int d0 = blockIdx.x * DT;

    const float* __restrict__ de = g_S + (size_t)b * MROWS * LSEQ;
    const float* __restrict__ Bu = de + (size_t)1024 * LSEQ;
    const float* __restrict__ Cu = de + (size_t)1088 * LSEQ;
    const float* __restrict__ ub = u + (size_t)b * DMODEL * LSEQ;

    __shared__ __align__(16) float sBu[TL][SBS];
    __shared__ __align__(16) float sCu[TL][SBS];
    __shared__ __align__(16) float sDe[DT][SDS];
    __shared__ __align__(16) float sU [DT][SDS];
    __shared__ __align__(16) float sY [DT][SDS];

    const int tid = threadIdx.x;
    const int dl  = tid >> 3;
    const int c   = tid & 7;
    const int n0  = c * 8;

    uint64_t A2[4];
#pragma unroll
    for (int p = 0; p < 4; p++)
        A2[p] = *(const uint64_t*)&A[n0 + 2 * p];

    const float Dd = Dv[d0 + dl];
    uint64_t h2[4] = {0ull, 0ull, 0ull, 0ull};

    for (int l0 = 0; l0 < LSEQ; l0 += TL) {
        __syncthreads();
#pragma unroll
        for (int t = 0; t < 2; t++) {
            int f4 = tid + 256 * t;
            int n  = f4 >> 3;
            int q  = f4 & 7;
            float4 v = *(const float4*)(Bu + (size_t)n * LSEQ + l0 + q * 4);
            sBu[q * 4 + 0][n] = v.x; sBu[q * 4 + 1][n] = v.y;
            sBu[q * 4 + 2][n] = v.z; sBu[q * 4 + 3][n] = v.w;
            float4 w = *(const float4*)(Cu + (size_t)n * LSEQ + l0 + q * 4);
            sCu[q * 4 + 0][n] = w.x; sCu[q * 4 + 1][n] = w.y;
            sCu[q * 4 + 2][n] = w.z; sCu[q * 4 + 3][n] = w.w;
        }
        {
            int dd = tid >> 3, q = tid & 7;
            *(float4*)&sDe[dd][q * 4] = *(const float4*)(de + (size_t)(d0 + dd) * LSEQ + l0 + q * 4);
            *(float4*)&sU[dd][q * 4]  = *(const float4*)(ub + (size_t)(d0 + dd) * LSEQ + l0 + q * 4);
        }
        __syncthreads();

#pragma unroll 8
        for (int l = 0; l < TL; l++) {
            float ds = sDe[dl][l];
            float us = sU[dl][l];
            float du = ds * us;
            uint64_t d2  = dup2(ds);
            uint64_t du2 = dup2(du);
            uint64_t y2  = 0ull;
            const uint64_t* bup = (const uint64_t*)&sBu[l][n0];
            const uint64_t* cup = (const uint64_t*)&sCu[l][n0];
#pragma unroll
            for (int p = 0; p < 4; p++) {
                uint64_t dA = mul2(d2, A2[p]);
                uint64_t pb = mul2(du2, bup[p]);
                h2[p] = fma2(dA, h2[p], pb);
                y2    = fma2(cup[p], h2[p], y2);
            }
            float2 yf = u64_f2(y2);
            float yv = yf.x + yf.y;
#pragma unroll
            for (int m = 1; m < 8; m <<= 1)
                yv += __shfl_xor_sync(0xffffffffu, yv, m);
            if (c == 0) sY[dl][l] = yv;
        }
        __syncthreads();

        {
            int dd = tid >> 3, q = tid & 7;
            float4 yv = *(const float4*)&sY[dd][q * 4];
            float4 uv = *(const float4*)&sU[dd][q * 4];
            float4 o;
            o.x = yv.x + uv.x * Dd;
            o.y = yv.y + uv.y * Dd;
            o.z = yv.z + uv.z * Dd;
            o.w = yv.w + uv.w * Dd;
            *(float4*)(y + ((size_t)b * DMODEL + d0 + dd) * LSEQ + l0 + q * 4) = o;
        }
    }
}

// ---------------- host launcher ----------------
extern "C" void kernel_launch(void* const* d_in, const int* in_sizes, int n_in,
                              void* d_out, int out_size)
{
    const float* u  = nullptr;
    const float* A  = nullptr;
    const float* Bm = nullptr;
    const float* Cm = nullptr;
    const float* D  = nullptr;
    const float* De = nullptr;
    for (int i = 0; i < n_in; i++) {
        int s = in_sizes[i];
        const float* p = (const float*)d_in[i];
        if      (s == 8388608 && !u)  u  = p;
        else if (s == 64      && !A)  A  = p;
        else if (s == 65536) { if (!Bm) Bm = p; else if (!Cm) Cm = p; }
        else if (s == 1024    && !D)  D  = p;
        else if (s == 1048576 && !De) De = p;
    }
    float* y = (float*)d_out;
    (void)out_size;

    cudaFuncSetAttribute(gemm_mma_kernel,
                         cudaFuncAttributeMaxDynamicSharedMemorySize, SMEM_G);

    // 0) pack W = [Delta; Bm; Cm]
    pack_w_kernel<<<(MROWS * DMODEL + 255) / 256, 256>>>(De, Bm, Cm);

    // 1) tf32 mma.sync GEMM: g_S[b] = W @ u[b]
    {
        dim3 grid(LSEQ / BN, MROWS / BM, BATCH);   // 16 x 9 x 4 = 576 CTAs
        gemm_mma_kernel<<<grid, 256, SMEM_G>>>(u);
    }
    // 2) sequential scan + output
    {
        dim3 grid(DMODEL / DT, BATCH);             // 32 x 4
        scan_kernel<<<grid, 256>>>(u, A, D, y);
    }
}

// round 10
// speedup vs baseline: 1.5420x; 1.0526x over previous
#include <cuda_runtime.h>
#include <cstdint>

#define BATCH  4
#define DMODEL 1024
#define NSTATE 64
#define LSEQ   2048
#define MROWS  1152   // 1024 (Delta) + 64 (Bm) + 64 (Cm)

// ---------------- device scratch (allocation-free) ----------------
__device__ __align__(256) float g_W[MROWS * DMODEL];                 // tf32-rounded [Delta; Bm; Cm]
__device__ __align__(256) float g_U[(size_t)BATCH * DMODEL * LSEQ];  // tf32-rounded u (GEMM only)
__device__ __align__(256) float g_S[(size_t)BATCH * MROWS * LSEQ];   // [delta; Bu; Cu] per batch

// ---------------- f32x2 packed helpers (scan) ----------------
__device__ __forceinline__ uint64_t dup2(float x) {
    uint64_t r; asm("mov.b64 %0, {%1, %1};" : "=l"(r) : "f"(x)); return r;
}
__device__ __forceinline__ uint64_t mul2(uint64_t a, uint64_t b) {
    uint64_t r; asm("mul.rn.f32x2 %0, %1, %2;" : "=l"(r) : "l"(a), "l"(b)); return r;
}
__device__ __forceinline__ uint64_t fma2(uint64_t a, uint64_t b, uint64_t c) {
    uint64_t r; asm("fma.rn.f32x2 %0, %1, %2, %3;" : "=l"(r) : "l"(a), "l"(b), "l"(c)); return r;
}
__device__ __forceinline__ float2 u64_f2(uint64_t v) {
    float2 f; asm("mov.b64 {%0, %1}, %2;" : "=f"(f.x), "=f"(f.y) : "l"(v)); return f;
}

// ---------------- tf32 helpers ----------------
__device__ __forceinline__ float tf32r(float x) {
    uint32_t r; asm("cvt.rna.tf32.f32 %0, %1;" : "=r"(r) : "f"(x));
    return __uint_as_float(r);
}

// mma.sync m16n8k8 tf32 (base ISA, compiles for plain sm_103)
__device__ __forceinline__ void mma_tf32(float* c, const uint32_t* a, const uint32_t* b) {
    asm volatile("mma.sync.aligned.m16n8k8.row.col.f32.tf32.tf32.f32 "
        "{%0,%1,%2,%3}, {%4,%5,%6,%7}, {%8,%9}, {%0,%1,%2,%3};"
        : "+f"(c[0]), "+f"(c[1]), "+f"(c[2]), "+f"(c[3])
        : "r"(a[0]), "r"(a[1]), "r"(a[2]), "r"(a[3]), "r"(b[0]), "r"(b[1]));
}

__device__ __forceinline__ void cpasync16(uint32_t dst, const void* src) {
    asm volatile("cp.async.cg.shared.global [%0], [%1], 16;" :: "r"(dst), "l"(src) : "memory");
}
__device__ __forceinline__ uint32_t smem_u32(const void* p) {
    uint32_t a;
    asm("{ .reg .u64 t; cvta.to.shared.u64 t, %1; cvt.u32.u64 %0, t; }" : "=r"(a) : "l"(p));
    return a;
}
#define CP_COMMIT() asm volatile("cp.async.commit_group;" ::: "memory")

// ---------------- kernel 0: pack + tf32-round W = [Delta; Bm; Cm] ----------------
__global__ __launch_bounds__(256) void pack_w_kernel(
    const float* __restrict__ Delta, const float* __restrict__ Bm, const float* __restrict__ Cm)
{
    int i = blockIdx.x * 256 + threadIdx.x;
    if (i >= MROWS * DMODEL) return;
    int r = i >> 10, c = i & 1023;
    float v;
    if (r < 1024)      v = Delta[r * DMODEL + c];
    else if (r < 1088) v = Bm[(r - 1024) * DMODEL + c];
    else               v = Cm[(r - 1088) * DMODEL + c];
    g_W[i] = tf32r(v);
}

// ---------------- kernel 0b: tf32-round u -> g_U ----------------
__global__ __launch_bounds__(256) void round_u_kernel(const float* __restrict__ u)
{
    size_t i = (size_t)blockIdx.x * 256 + threadIdx.x;   // float4 index
    float4 v = ((const float4*)u)[i];
    v.x = tf32r(v.x); v.y = tf32r(v.y); v.z = tf32r(v.z); v.w = tf32r(v.w);
    ((float4*)g_U)[i] = v;
}

// ---------------- kernel 1: tf32 mma.sync GEMM  g_S[b] = g_W @ g_U[b] ----------------
#define BM 128
#define BN 128
#define BK 32
#define ASTR 36                  // A smem row stride (floats)
#define BSTR 136                 // B smem row stride (floats)
#define AF (BM * ASTR)           // 4608 floats
#define BF (BK * BSTR)           // 4352 floats
#define STF (AF + BF)            // 8960 floats per stage
#define SMEM_G (2 * STF * 4)     // 71680 bytes
#define NCHUNK (DMODEL / BK)     // 32

__device__ __forceinline__ void load_chunk_g(int tid, int c, int m0, int n0,
                                             const float* __restrict__ Ub,
                                             uint32_t aSm, uint32_t bSm)
{
    const float* Wt = g_W + (size_t)m0 * DMODEL + c * BK;
#pragma unroll
    for (int i = 0; i < 4; i++) {                 // A: 128 rows x 32 floats
        int t = tid + 256 * i;
        int r = t >> 3, j = t & 7;
        cpasync16(aSm + r * (ASTR * 4) + j * 16, Wt + (size_t)r * DMODEL + j * 4);
    }
    const float* Ut = Ub + (size_t)(c * BK) * LSEQ + n0;
#pragma unroll
    for (int i = 0; i < 4; i++) {                 // B: 32 rows x 128 floats
        int t = tid + 256 * i;
        int k = t >> 5, j = t & 31;
        cpasync16(bSm + k * (BSTR * 4) + j * 16, Ut + (size_t)k * LSEQ + j * 4);
    }
}

__global__ __launch_bounds__(256, 2) void gemm_mma_kernel()
{
    extern __shared__ __align__(16) float sm[];
    const int tid  = threadIdx.x;
    const int wid  = tid >> 5, lane = tid & 31;
    const int wm   = wid & 3, wn = wid >> 2;      // 4 m-warps x 2 n-warps
    const int g    = lane >> 2, tg = lane & 3;

    const int b  = blockIdx.z;
    const int m0 = blockIdx.y * BM;
    const int n0 = blockIdx.x * BN;
    const float* __restrict__ Ub = g_U + (size_t)b * DMODEL * LSEQ;
    float* __restrict__ Cb = g_S + (size_t)b * MROWS * LSEQ;

    const uint32_t sb = smem_u32(sm);
    const uint32_t aSm[2] = {sb, sb + STF * 4};
    const uint32_t bSm[2] = {sb + AF * 4, sb + STF * 4 + AF * 4};
    const uint32_t* aP[2] = {(const uint32_t*)sm, (const uint32_t*)(sm + STF)};
    const uint32_t* bP[2] = {(const uint32_t*)(sm + AF), (const uint32_t*)(sm + STF + AF)};

    float acc[2][8][4];
#pragma unroll
    for (int mt = 0; mt < 2; mt++)
#pragma unroll
        for (int nt = 0; nt < 8; nt++)
#pragma unroll
            for (int q = 0; q < 4; q++) acc[mt][nt][q] = 0.f;

    load_chunk_g(tid, 0, m0, n0, Ub, aSm[0], bSm[0]);
    CP_COMMIT();

    for (int c = 0; c < NCHUNK; c++) {
        const int s = c & 1;
        if (c + 1 < NCHUNK) {
            load_chunk_g(tid, c + 1, m0, n0, Ub, aSm[1 - s], bSm[1 - s]);
            CP_COMMIT();
            asm volatile("cp.async.wait_group 1;" ::: "memory");
        } else {
            asm volatile("cp.async.wait_group 0;" ::: "memory");
        }
        __syncthreads();

        const uint32_t* As = aP[s];
        const uint32_t* Bs = bP[s];
#pragma unroll
        for (int ks = 0; ks < 4; ks++) {
            const int k0 = ks * 8;
            uint32_t af[2][4];
#pragma unroll
            for (int mt = 0; mt < 2; mt++) {
                int row = wm * 32 + mt * 16;
                af[mt][0] = As[(row + g)     * ASTR + k0 + tg];
                af[mt][1] = As[(row + g + 8) * ASTR + k0 + tg];
                af[mt][2] = As[(row + g)     * ASTR + k0 + tg + 4];
                af[mt][3] = As[(row + g + 8) * ASTR + k0 + tg + 4];
            }
            uint32_t bf[8][2];
#pragma unroll
            for (int nt = 0; nt < 8; nt++) {
                int col = wn * 64 + nt * 8 + g;
                bf[nt][0] = Bs[(k0 + tg)     * BSTR + col];
                bf[nt][1] = Bs[(k0 + tg + 4) * BSTR + col];
            }
#pragma unroll
            for (int mt = 0; mt < 2; mt++)
#pragma unroll
                for (int nt = 0; nt < 8; nt++)
                    mma_tf32(acc[mt][nt], af[mt], bf[nt]);
        }
        __syncthreads();
    }

    // epilogue: direct STG
#pragma unroll
    for (int mt = 0; mt < 2; mt++) {
        int row0 = m0 + wm * 32 + mt * 16 + g;
#pragma unroll
        for (int nt = 0; nt < 8; nt++) {
            int col = n0 + wn * 64 + nt * 8 + 2 * tg;
            float2 v0 = {acc[mt][nt][0], acc[mt][nt][1]};
            float2 v1 = {acc[mt][nt][2], acc[mt][nt][3]};
            *(float2*)(Cb + (size_t)row0 * LSEQ + col)       = v0;
            *(float2*)(Cb + (size_t)(row0 + 8) * LSEQ + col) = v1;
        }
    }
}

// ---------------- kernel 2: sequential scan over L ----------------
// Per-step y reduction via fire-and-forget STS into sYp (no shfl chain);
// 8-way sum folded into the vectorized writeback phase.
#define DT  32
#define TL  32
#define SBS 66
#define SDS 36

__global__ __launch_bounds__(256) void scan_kernel(
    const float* __restrict__ u, const float* __restrict__ A,
    const float* __restrict__ Dv, float* __restrict__ y)
{
    const int b  = blockIdx.y;
    const int d0 = blockIdx.x * DT;

    const float* __restrict__ de = g_S + (size_t)b * MROWS * LSEQ;
    const float* __restrict__ Bu = de + (size_t)1024 * LSEQ;
    const float* __restrict__ Cu = de + (size_t)1088 * LSEQ;
    const float* __restrict__ ub = u + (size_t)b * DMODEL * LSEQ;

    __shared__ __align__(16) float sBu[TL][SBS];
    __shared__ __align__(16) float sCu[TL][SBS];
    __shared__ __align__(16) float sDe[DT][SDS];
    __shared__ __align__(16) float sU [DT][SDS];
    __shared__ __align__(16) float sYp[TL][DT * 8];   // per-(l, d, c) partials, 32KB

    const int tid = threadIdx.x;
    const int dl  = tid >> 3;
    const int c   = tid & 7;
    const int n0  = c * 8;

    uint64_t A2[4];
#pragma unroll
    for (int p = 0; p < 4; p++)
        A2[p] = *(const uint64_t*)&A[n0 + 2 * p];

    const float Dd = Dv[d0 + (tid >> 3)];
    uint64_t h2[4] = {0ull, 0ull, 0ull, 0ull};

    for (int l0 = 0; l0 < LSEQ; l0 += TL) {
        __syncthreads();
#pragma unroll
        for (int t = 0; t < 2; t++) {
            int f4 = tid + 256 * t;
            int n  = f4 >> 3;
            int q  = f4 & 7;
            float4 v = *(const float4*)(Bu + (size_t)n * LSEQ + l0 + q * 4);
            sBu[q * 4 + 0][n] = v.x; sBu[q * 4 + 1][n] = v.y;
            sBu[q * 4 + 2][n] = v.z; sBu[q * 4 + 3][n] = v.w;
            float4 w = *(const float4*)(Cu + (size_t)n * LSEQ + l0 + q * 4);
            sCu[q * 4 + 0][n] = w.x; sCu[q * 4 + 1][n] = w.y;
            sCu[q * 4 + 2][n] = w.z; sCu[q * 4 + 3][n] = w.w;
        }
        {
            int dd = tid >> 3, q = tid & 7;
            *(float4*)&sDe[dd][q * 4] = *(const float4*)(de + (size_t)(d0 + dd) * LSEQ + l0 + q * 4);
            *(float4*)&sU[dd][q * 4]  = *(const float4*)(ub + (size_t)(d0 + dd) * LSEQ + l0 + q * 4);
        }
        __syncthreads();

#pragma unroll 8
        for (int l = 0; l < TL; l++) {
            float ds = sDe[dl][l];
            float us = sU[dl][l];
            float du = ds * us;
            uint64_t d2  = dup2(ds);
            uint64_t du2 = dup2(du);
            uint64_t y2  = 0ull;
            const uint64_t* bup = (const uint64_t*)&sBu[l][n0];
            const uint64_t* cup = (const uint64_t*)&sCu[l][n0];
#pragma unroll
            for (int p = 0; p < 4; p++) {
                uint64_t dA = mul2(d2, A2[p]);
                uint64_t pb = mul2(du2, bup[p]);
                h2[p] = fma2(dA, h2[p], pb);
                y2    = fma2(cup[p], h2[p], y2);
            }
            float2 yf = u64_f2(y2);
            sYp[l][dl * 8 + c] = yf.x + yf.y;    // fire-and-forget partial
        }
        __syncthreads();

        // writeback: reduce 8 partials per (d, l), add u*D
        {
            int dd = tid >> 3, q = tid & 7;
            float4 uv = *(const float4*)&sU[dd][q * 4];
            float4 o;
#pragma unroll
            for (int i = 0; i < 4; i++) {
                int l = q * 4 + i;
                const float4* pp = (const float4*)&sYp[l][dd * 8];
                float4 p0 = pp[0], p1 = pp[1];
                float s = ((p0.x + p0.y) + (p0.z + p0.w)) +
                          ((p1.x + p1.y) + (p1.z + p1.w));
                (&o.x)[i] = s;
            }
            o.x += uv.x * Dd; o.y += uv.y * Dd;
            o.z += uv.z * Dd; o.w += uv.w * Dd;
            *(float4*)(y + ((size_t)b * DMODEL + d0 + dd) * LSEQ + l0 + q * 4) = o;
        }
    }
}

// ---------------- host launcher ----------------
extern "C" void kernel_launch(void* const* d_in, const int* in_sizes, int n_in,
                              void* d_out, int out_size)
{
    const float* u  = nullptr;
    const float* A  = nullptr;
    const float* Bm = nullptr;
    const float* Cm = nullptr;
    const float* D  = nullptr;
    const float* De = nullptr;
    for (int i = 0; i < n_in; i++) {
        int s = in_sizes[i];
        const float* p = (const float*)d_in[i];
        if      (s == 8388608 && !u)  u  = p;
        else if (s == 64      && !A)  A  = p;
        else if (s == 65536) { if (!Bm) Bm = p; else if (!Cm) Cm = p; }
        else if (s == 1024    && !D)  D  = p;
        else if (s == 1048576 && !De) De = p;
    }
    float* y = (float*)d_out;
    (void)out_size;

    cudaFuncSetAttribute(gemm_mma_kernel,
                         cudaFuncAttributeMaxDynamicSharedMemorySize, SMEM_G);

    // 0) pack + tf32-round W; tf32-round u
    pack_w_kernel<<<(MROWS * DMODEL + 255) / 256, 256>>>(De, Bm, Cm);
    round_u_kernel<<<(BATCH * DMODEL * LSEQ / 4 + 255) / 256, 256>>>(u);

    // 1) tf32 mma.sync GEMM: g_S[b] = W @ u[b]
    {
        dim3 grid(LSEQ / BN, MROWS / BM, BATCH);   // 16 x 9 x 4 = 576 CTAs
        gemm_mma_kernel<<<grid, 256, SMEM_G>>>();
    }
    // 2) sequential scan + output
    {
        dim3 grid(DMODEL / DT, BATCH);             // 32 x 4
        scan_kernel<<<grid, 256>>>(u, A, D, y);
    }
}

// round 11
// speedup vs baseline: 1.6490x; 1.0694x over previous
#include <cuda_runtime.h>
#include <cstdint>

#define BATCH  4
#define DMODEL 1024
#define NSTATE 64
#define LSEQ   2048
#define MROWS  1152   // 1024 (Delta) + 64 (Bm) + 64 (Cm)

// ---------------- device scratch (allocation-free) ----------------
__device__ __align__(256) float g_W[MROWS * DMODEL];                 // tf32-rounded [Delta; Bm; Cm]
__device__ __align__(256) float g_U[(size_t)BATCH * DMODEL * LSEQ];  // tf32-rounded u (GEMM only)
__device__ __align__(256) float g_S[(size_t)BATCH * MROWS * LSEQ];   // [delta; Bu; Cu] per batch

// ---------------- f32x2 packed helpers (scan) ----------------
__device__ __forceinline__ uint64_t dup2(float x) {
    uint64_t r; asm("mov.b64 %0, {%1, %1};" : "=l"(r) : "f"(x)); return r;
}
__device__ __forceinline__ uint64_t mul2(uint64_t a, uint64_t b) {
    uint64_t r; asm("mul.rn.f32x2 %0, %1, %2;" : "=l"(r) : "l"(a), "l"(b)); return r;
}
__device__ __forceinline__ uint64_t fma2(uint64_t a, uint64_t b, uint64_t c) {
    uint64_t r; asm("fma.rn.f32x2 %0, %1, %2, %3;" : "=l"(r) : "l"(a), "l"(b), "l"(c)); return r;
}
__device__ __forceinline__ float2 u64_f2(uint64_t v) {
    float2 f; asm("mov.b64 {%0, %1}, %2;" : "=f"(f.x), "=f"(f.y) : "l"(v)); return f;
}

// ---------------- tf32 helpers ----------------
__device__ __forceinline__ float tf32r(float x) {
    uint32_t r; asm("cvt.rna.tf32.f32 %0, %1;" : "=r"(r) : "f"(x));
    return __uint_as_float(r);
}

// mma.sync m16n8k8 tf32 (base ISA, compiles for plain sm_103)
__device__ __forceinline__ void mma_tf32(float* c, const uint32_t* a, const uint32_t* b) {
    asm volatile("mma.sync.aligned.m16n8k8.row.col.f32.tf32.tf32.f32 "
        "{%0,%1,%2,%3}, {%4,%5,%6,%7}, {%8,%9}, {%0,%1,%2,%3};"
        : "+f"(c[0]), "+f"(c[1]), "+f"(c[2]), "+f"(c[3])
        : "r"(a[0]), "r"(a[1]), "r"(a[2]), "r"(a[3]), "r"(b[0]), "r"(b[1]));
}

__device__ __forceinline__ void cpasync16(uint32_t dst, const void* src) {
    asm volatile("cp.async.cg.shared.global [%0], [%1], 16;" :: "r"(dst), "l"(src) : "memory");
}
__device__ __forceinline__ uint32_t smem_u32(const void* p) {
    uint32_t a;
    asm("{ .reg .u64 t; cvta.to.shared.u64 t, %1; cvt.u32.u64 %0, t; }" : "=r"(a) : "l"(p));
    return a;
}
#define CP_COMMIT() asm volatile("cp.async.commit_group;" ::: "memory")

// ---------------- kernel 0: pack + tf32-round W = [Delta; Bm; Cm] ----------------
__global__ __launch_bounds__(256) void pack_w_kernel(
    const float* __restrict__ Delta, const float* __restrict__ Bm, const float* __restrict__ Cm)
{
    int i = blockIdx.x * 256 + threadIdx.x;
    if (i >= MROWS * DMODEL) return;
    int r = i >> 10, c = i & 1023;
    float v;
    if (r < 1024)      v = Delta[r * DMODEL + c];
    else if (r < 1088) v = Bm[(r - 1024) * DMODEL + c];
    else               v = Cm[(r - 1088) * DMODEL + c];
    g_W[i] = tf32r(v);
}

// ---------------- kernel 0b: tf32-round u -> g_U ----------------
__global__ __launch_bounds__(256) void round_u_kernel(const float* __restrict__ u)
{
    size_t i = (size_t)blockIdx.x * 256 + threadIdx.x;   // float4 index
    float4 v = ((const float4*)u)[i];
    v.x = tf32r(v.x); v.y = tf32r(v.y); v.z = tf32r(v.z); v.w = tf32r(v.w);
    ((float4*)g_U)[i] = v;
}

// ---------------- kernel 1: tf32 mma.sync GEMM  g_S[b] = g_W @ g_U[b] ----------------
#define BM 128
#define BN 128
#define BK 32
#define ASTR 36                  // A smem row stride (floats)
#define BSTR 136                 // B smem row stride (floats)
#define AF (BM * ASTR)           // 4608 floats
#define BF (BK * BSTR)           // 4352 floats
#define STF (AF + BF)            // 8960 floats per stage
#define SMEM_G (2 * STF * 4)     // 71680 bytes
#define NCHUNK (DMODEL / BK)     // 32

__device__ __forceinline__ void load_chunk_g(int tid, int c, int m0, int n0,
                                             const float* __restrict__ Ub,
                                             uint32_t aSm, uint32_t bSm)
{
    const float* Wt = g_W + (size_t)m0 * DMODEL + c * BK;
#pragma unroll
    for (int i = 0; i < 4; i++) {                 // A: 128 rows x 32 floats
        int t = tid + 256 * i;
        int r = t >> 3, j = t & 7;
        cpasync16(aSm + r * (ASTR * 4) + j * 16, Wt + (size_t)r * DMODEL + j * 4);
    }
    const float* Ut = Ub + (size_t)(c * BK) * LSEQ + n0;
#pragma unroll
    for (int i = 0; i < 4; i++) {                 // B: 32 rows x 128 floats
        int t = tid + 256 * i;
        int k = t >> 5, j = t & 31;
        cpasync16(bSm + k * (BSTR * 4) + j * 16, Ut + (size_t)k * LSEQ + j * 4);
    }
}

__global__ __launch_bounds__(256, 2) void gemm_mma_kernel()
{
    extern __shared__ __align__(16) float sm[];
    const int tid  = threadIdx.x;
    const int wid  = tid >> 5, lane = tid & 31;
    const int wm   = wid & 3, wn = wid >> 2;      // 4 m-warps x 2 n-warps
    const int g    = lane >> 2, tg = lane & 3;

    const int b  = blockIdx.z;
    const int m0 = blockIdx.y * BM;
    const int n0 = blockIdx.x * BN;
    const float* __restrict__ Ub = g_U + (size_t)b * DMODEL * LSEQ;
    float* __restrict__ Cb = g_S + (size_t)b * MROWS * LSEQ;

    const uint32_t sb = smem_u32(sm);
    const uint32_t aSm[2] = {sb, sb + STF * 4};
    const uint32_t bSm[2] = {sb + AF * 4, sb + STF * 4 + AF * 4};
    const uint32_t* aP[2] = {(const uint32_t*)sm, (const uint32_t*)(sm + STF)};
    const uint32_t* bP[2] = {(const uint32_t*)(sm + AF), (const uint32_t*)(sm + STF + AF)};

    float acc[2][8][4];
#pragma unroll
    for (int mt = 0; mt < 2; mt++)
#pragma unroll
        for (int nt = 0; nt < 8; nt++)
#pragma unroll
            for (int q = 0; q < 4; q++) acc[mt][nt][q] = 0.f;

    load_chunk_g(tid, 0, m0, n0, Ub, aSm[0], bSm[0]);
    CP_COMMIT();

    for (int c = 0; c < NCHUNK; c++) {
        const int s = c & 1;
        if (c + 1 < NCHUNK) {
            load_chunk_g(tid, c + 1, m0, n0, Ub, aSm[1 - s], bSm[1 - s]);
            CP_COMMIT();
            asm volatile("cp.async.wait_group 1;" ::: "memory");
        } else {
            asm volatile("cp.async.wait_group 0;" ::: "memory");
        }
        __syncthreads();

        const uint32_t* As = aP[s];
        const uint32_t* Bs = bP[s];
#pragma unroll
        for (int ks = 0; ks < 4; ks++) {
            const int k0 = ks * 8;
            uint32_t af[2][4];
#pragma unroll
            for (int mt = 0; mt < 2; mt++) {
                int row = wm * 32 + mt * 16;
                af[mt][0] = As[(row + g)     * ASTR + k0 + tg];
                af[mt][1] = As[(row + g + 8) * ASTR + k0 + tg];
                af[mt][2] = As[(row + g)     * ASTR + k0 + tg + 4];
                af[mt][3] = As[(row + g + 8) * ASTR + k0 + tg + 4];
            }
            uint32_t bf[8][2];
#pragma unroll
            for (int nt = 0; nt < 8; nt++) {
                int col = wn * 64 + nt * 8 + g;
                bf[nt][0] = Bs[(k0 + tg)     * BSTR + col];
                bf[nt][1] = Bs[(k0 + tg + 4) * BSTR + col];
            }
#pragma unroll
            for (int mt = 0; mt < 2; mt++)
#pragma unroll
                for (int nt = 0; nt < 8; nt++)
                    mma_tf32(acc[mt][nt], af[mt], bf[nt]);
        }
        __syncthreads();
    }

    // epilogue: direct STG
#pragma unroll
    for (int mt = 0; mt < 2; mt++) {
        int row0 = m0 + wm * 32 + mt * 16 + g;
#pragma unroll
        for (int nt = 0; nt < 8; nt++) {
            int col = n0 + wn * 64 + nt * 8 + 2 * tg;
            float2 v0 = {acc[mt][nt][0], acc[mt][nt][1]};
            float2 v1 = {acc[mt][nt][2], acc[mt][nt][3]};
            *(float2*)(Cb + (size_t)row0 * LSEQ + col)       = v0;
            *(float2*)(Cb + (size_t)(row0 + 8) * LSEQ + col) = v1;
        }
    }
}

// ---------------- kernel 2: sequential scan over L ----------------
// 16 threads per d, 4 n-states per thread. Block = 256 thr = 16 d.
// Grid = 64 x 4 = 256 blocks -> ~2 CTAs/SM, 2x warps vs previous round.
#define DT  16      // d per block
#define TL  32      // l per tile
#define SBS 68      // sBu/sCu row stride (floats), 16B-aligned rows
#define SDS 36      // sDe/sU row stride

// dynamic smem layout (floats)
#define OF_BU 0
#define OF_CU (OF_BU + TL * SBS)            // 2176
#define OF_DE (OF_CU + TL * SBS)            // 4352
#define OF_U  (OF_DE + DT * SDS)            // 4928
#define OF_YP (OF_U + DT * SDS)             // 5504
#define SCAN_FLOATS (OF_YP + TL * 256)      // 13696
#define SMEM_SCAN (SCAN_FLOATS * 4)         // 54784 bytes

__global__ __launch_bounds__(256) void scan_kernel(
    const float* __restrict__ u, const float* __restrict__ A,
    const float* __restrict__ Dv, float* __restrict__ y)
{
    extern __shared__ __align__(16) float sw[];
    float* sBu = sw + OF_BU;     // [TL][SBS]
    float* sCu = sw + OF_CU;     // [TL][SBS]
    float* sDe = sw + OF_DE;     // [DT][SDS]
    float* sU  = sw + OF_U;      // [DT][SDS]
    float* sYp = sw + OF_YP;     // [TL][256]

    const int b  = blockIdx.y;
    const int d0 = blockIdx.x * DT;

    const float* __restrict__ de = g_S + (size_t)b * MROWS * LSEQ;
    const float* __restrict__ Bu = de + (size_t)1024 * LSEQ;
    const float* __restrict__ Cu = de + (size_t)1088 * LSEQ;
    const float* __restrict__ ub = u + (size_t)b * DMODEL * LSEQ;

    const int tid = threadIdx.x;
    const int dl  = tid >> 4;    // 0..15 local d
    const int c   = tid & 15;    // 0..15 n-chunk
    const int n0  = c * 4;       // 4 n per thread

    uint64_t A2[2];
#pragma unroll
    for (int p = 0; p < 2; p++)
        A2[p] = *(const uint64_t*)&A[n0 + 2 * p];

    const float Dd = Dv[d0 + dl];
    uint64_t h2[2] = {0ull, 0ull};

    for (int l0 = 0; l0 < LSEQ; l0 += TL) {
        __syncthreads();   // previous tile fully consumed (incl. writeback reads)

        // Bu/Cu tile: 64 n x 32 l, transposed to [l][n]
#pragma unroll
        for (int t = 0; t < 2; t++) {
            int f4 = tid + 256 * t;    // 0..511
            int n  = f4 >> 3;          // 0..63
            int q  = f4 & 7;           // l quad
            float4 v = *(const float4*)(Bu + (size_t)n * LSEQ + l0 + q * 4);
            sBu[(q * 4 + 0) * SBS + n] = v.x; sBu[(q * 4 + 1) * SBS + n] = v.y;
            sBu[(q * 4 + 2) * SBS + n] = v.z; sBu[(q * 4 + 3) * SBS + n] = v.w;
            float4 w = *(const float4*)(Cu + (size_t)n * LSEQ + l0 + q * 4);
            sCu[(q * 4 + 0) * SBS + n] = w.x; sCu[(q * 4 + 1) * SBS + n] = w.y;
            sCu[(q * 4 + 2) * SBS + n] = w.z; sCu[(q * 4 + 3) * SBS + n] = w.w;
        }
        // delta / u tiles: 16 d x 32 l
        if (tid < 128) {
            int dd = tid >> 3, q = tid & 7;
            *(float4*)&sDe[dd * SDS + q * 4] =
                *(const float4*)(de + (size_t)(d0 + dd) * LSEQ + l0 + q * 4);
            *(float4*)&sU[dd * SDS + q * 4] =
                *(const float4*)(ub + (size_t)(d0 + dd) * LSEQ + l0 + q * 4);
        }
        __syncthreads();

#pragma unroll 8
        for (int l = 0; l < TL; l++) {
            float ds = sDe[dl * SDS + l];
            float us = sU[dl * SDS + l];
            float du = ds * us;
            uint64_t d2  = dup2(ds);
            uint64_t du2 = dup2(du);
            ulonglong2 bu2 = *(const ulonglong2*)&sBu[l * SBS + n0];
            ulonglong2 cu2 = *(const ulonglong2*)&sCu[l * SBS + n0];
            uint64_t dA0 = mul2(d2, A2[0]);
            uint64_t dA1 = mul2(d2, A2[1]);
            h2[0] = fma2(dA0, h2[0], mul2(du2, bu2.x));
            h2[1] = fma2(dA1, h2[1], mul2(du2, bu2.y));
            uint64_t y2 = fma2(cu2.y, h2[1], mul2(cu2.x, h2[0]));
            float2 yf = u64_f2(y2);
            sYp[l * 256 + dl * 16 + c] = yf.x + yf.y;   // fire-and-forget partial
        }
        __syncthreads();

        // writeback: reduce 16 partials per (d, l), add u*D
        if (tid < 128) {
            int dd = tid >> 3, q = tid & 7;
            float4 uv = *(const float4*)&sU[dd * SDS + q * 4];
            float4 o;
#pragma unroll
            for (int i = 0; i < 4; i++) {
                int l = q * 4 + i;
                const float4* pp = (const float4*)&sYp[l * 256 + dd * 16];
                float4 p0 = pp[0], p1 = pp[1], p2 = pp[2], p3 = pp[3];
                float s = (((p0.x + p0.y) + (p0.z + p0.w)) +
                           ((p1.x + p1.y) + (p1.z + p1.w))) +
                          (((p2.x + p2.y) + (p2.z + p2.w)) +
                           ((p3.x + p3.y) + (p3.z + p3.w)));
                (&o.x)[i] = s;
            }
            float Ddw = Dv[d0 + dd];
            o.x += uv.x * Ddw; o.y += uv.y * Ddw;
            o.z += uv.z * Ddw; o.w += uv.w * Ddw;
            *(float4*)(y + ((size_t)b * DMODEL + d0 + dd) * LSEQ + l0 + q * 4) = o;
        }
    }
    (void)Dd;
}

// ---------------- host launcher ----------------
extern "C" void kernel_launch(void* const* d_in, const int* in_sizes, int n_in,
                              void* d_out, int out_size)
{
    const float* u  = nullptr;
    const float* A  = nullptr;
    const float* Bm = nullptr;
    const float* Cm = nullptr;
    const float* D  = nullptr;
    const float* De = nullptr;
    for (int i = 0; i < n_in; i++) {
        int s = in_sizes[i];
        const float* p = (const float*)d_in[i];
        if      (s == 8388608 && !u)  u  = p;
        else if (s == 64      && !A)  A  = p;
        else if (s == 65536) { if (!Bm) Bm = p; else if (!Cm) Cm = p; }
        else if (s == 1024    && !D)  D  = p;
        else if (s == 1048576 && !De) De = p;
    }
    float* y = (float*)d_out;
    (void)out_size;

    cudaFuncSetAttribute(gemm_mma_kernel,
                         cudaFuncAttributeMaxDynamicSharedMemorySize, SMEM_G);
    cudaFuncSetAttribute(scan_kernel,
                         cudaFuncAttributeMaxDynamicSharedMemorySize, SMEM_SCAN);

    // 0) pack + tf32-round W; tf32-round u
    pack_w_kernel<<<(MROWS * DMODEL + 255) / 256, 256>>>(De, Bm, Cm);
    round_u_kernel<<<(BATCH * DMODEL * LSEQ / 4 + 255) / 256, 256>>>(u);

    // 1) tf32 mma.sync GEMM: g_S[b] = W @ u[b]
    {
        dim3 grid(LSEQ / BN, MROWS / BM, BATCH);   // 16 x 9 x 4 = 576 CTAs
        gemm_mma_kernel<<<grid, 256, SMEM_G>>>();
    }
    // 2) sequential scan + output
    {
        dim3 grid(DMODEL / DT, BATCH);             // 64 x 4 = 256 blocks
        scan_kernel<<<grid, 256, SMEM_SCAN>>>(u, A, D, y);
    }
}